// round 1
// baseline (speedup 1.0000x reference)
#include <cuda_runtime.h>
#include <math.h>

#define N_ 32
#define O_ 2048
#define I_ 4096
#define I4_ (I_/4)          // 1024
#define E_ 3
#define D_ 8
#define H_ 16
#define SELF_W 0.7f
#define OB 4                // o-rows per thread

// Scratch (no allocs allowed): per-(n,i) scaled weights and per-i scale for target_W
__device__ float4 g_wnm4[N_ * I4_];
__device__ float4 g_a4[I4_];

// ---------------------------------------------------------------------------
// Prologue: attention weights, normalizers, bias output. One block, trivial cost.
// ---------------------------------------------------------------------------
__global__ void prologue_kernel(const float* __restrict__ edge_feats,
                                const float* __restrict__ node_feats,
                                const float* __restrict__ W1e, const float* __restrict__ b1e,
                                const float* __restrict__ W2e, const float* __restrict__ b2e,
                                const float* __restrict__ W1n, const float* __restrict__ b1n,
                                const float* __restrict__ W2n, const float* __restrict__ b2n,
                                const float* __restrict__ target_b,
                                const float* __restrict__ neighbor_b,
                                const int*   __restrict__ target_mask,
                                const int*   __restrict__ neighbor_masks,
                                float* __restrict__ out_b)
{
    __shared__ float w_s[N_];
    const int tid = threadIdx.x;

    if (tid < N_) {
        const int n = tid;
        // edge MLP: sigmoid( tanh(ef @ W1e + b1e) @ W2e + b2e )
        float logit_e = b2e[0];
        #pragma unroll
        for (int h = 0; h < H_; h++) {
            float acc = b1e[h];
            #pragma unroll
            for (int e = 0; e < E_; e++)
                acc += edge_feats[n * E_ + e] * W1e[e * H_ + h];
            logit_e += tanhf(acc) * W2e[h];
        }
        const float score = 1.f / (1.f + expf(-logit_e));

        // node MLP
        float logit_n = b2n[0];
        #pragma unroll
        for (int h = 0; h < H_; h++) {
            float acc = b1n[h];
            #pragma unroll
            for (int d = 0; d < D_; d++)
                acc += node_feats[n * D_ + d] * W1n[d * H_ + h];
            logit_n += tanhf(acc) * W2n[h];
        }
        const float cond = 1.f / (1.f + expf(-logit_n));

        // softmax over the 32 lanes of warp 0
        const float s = score * cond;
        float m = s;
        #pragma unroll
        for (int off = 16; off; off >>= 1)
            m = fmaxf(m, __shfl_xor_sync(0xffffffffu, m, off));
        const float ex = expf(s - m);
        float sum = ex;
        #pragma unroll
        for (int off = 16; off; off >>= 1)
            sum += __shfl_xor_sync(0xffffffffu, sum, off);
        w_s[n] = (1.f - SELF_W) * ex / sum;   // per-neighbor weight w[n]
    }
    __syncthreads();

    // per-column normalizer; store pre-scaled coefficients
    float* g_wnm = (float*)g_wnm4;
    float* g_a   = (float*)g_a4;
    for (int i = tid; i < I_; i += blockDim.x) {
        const float tm = (float)target_mask[i];
        float wn[N_];
        float norm = 1e-8f + SELF_W * tm;
        #pragma unroll
        for (int n = 0; n < N_; n++) {
            wn[n] = w_s[n] * (float)neighbor_masks[n * I_ + i];
            norm += wn[n];
        }
        const float inv = 1.f / norm;
        g_a[i] = SELF_W * tm * inv;
        #pragma unroll
        for (int n = 0; n < N_; n++)
            g_wnm[n * I_ + i] = wn[n] * inv;
    }

    // bias output (unnormalized branch)
    for (int o = tid; o < O_; o += blockDim.x) {
        float acc = SELF_W * target_b[o];
        #pragma unroll
        for (int n = 0; n < N_; n++)
            acc += w_s[n] * neighbor_b[n * O_ + o];
        out_b[o] = acc;
    }
}

// ---------------------------------------------------------------------------
// Main: out_W[o,i] = target_W[o,i]*a[i] + sum_n wnm[n,i]*neighbor_W[n,o,i]
// Each thread: one float4 column chunk x OB=4 consecutive o-rows (reuses wnm).
// ---------------------------------------------------------------------------
__global__ void __launch_bounds__(256)
main_kernel(const float4* __restrict__ tW,
            const float4* __restrict__ nW,
            float4* __restrict__ outW)
{
    const int idx = blockIdx.x * blockDim.x + threadIdx.x;   // [0, O_/OB * I4_)
    const int i4  = idx & (I4_ - 1);
    const int o0  = (idx >> 10) * OB;                        // I4_ = 1024 = 2^10

    const float4 a = g_a4[i4];
    float4 acc[OB];
    #pragma unroll
    for (int oo = 0; oo < OB; oo++) {
        const float4 t = tW[(size_t)(o0 + oo) * I4_ + i4];
        acc[oo].x = t.x * a.x;
        acc[oo].y = t.y * a.y;
        acc[oo].z = t.z * a.z;
        acc[oo].w = t.w * a.w;
    }

    #pragma unroll 4
    for (int n = 0; n < N_; n++) {
        const float4 wv = g_wnm4[n * I4_ + i4];              // L2-resident
        const size_t base = (size_t)n * (O_ * I4_);
        #pragma unroll
        for (int oo = 0; oo < OB; oo++) {
            const float4 Wv = nW[base + (size_t)(o0 + oo) * I4_ + i4];
            acc[oo].x += wv.x * Wv.x;
            acc[oo].y += wv.y * Wv.y;
            acc[oo].z += wv.z * Wv.z;
            acc[oo].w += wv.w * Wv.w;
        }
    }

    #pragma unroll
    for (int oo = 0; oo < OB; oo++)
        outW[(size_t)(o0 + oo) * I4_ + i4] = acc[oo];
}

// ---------------------------------------------------------------------------
extern "C" void kernel_launch(void* const* d_in, const int* in_sizes, int n_in,
                              void* d_out, int out_size)
{
    const float* edge_feats     = (const float*)d_in[0];
    const float* node_feats     = (const float*)d_in[1];
    const float* W1e            = (const float*)d_in[2];
    const float* b1e            = (const float*)d_in[3];
    const float* W2e            = (const float*)d_in[4];
    const float* b2e            = (const float*)d_in[5];
    const float* W1n            = (const float*)d_in[6];
    const float* b1n            = (const float*)d_in[7];
    const float* W2n            = (const float*)d_in[8];
    const float* b2n            = (const float*)d_in[9];
    const float* target_W       = (const float*)d_in[10];
    const float* neighbor_W     = (const float*)d_in[11];
    const float* target_b       = (const float*)d_in[12];
    const float* neighbor_b     = (const float*)d_in[13];
    const int*   target_mask    = (const int*)d_in[14];
    const int*   neighbor_masks = (const int*)d_in[15];

    float* out   = (float*)d_out;
    float* out_b = out + (size_t)O_ * I_;   // out_W flattened first, then out_b

    prologue_kernel<<<1, 256>>>(edge_feats, node_feats,
                                W1e, b1e, W2e, b2e,
                                W1n, b1n, W2n, b2n,
                                target_b, neighbor_b,
                                target_mask, neighbor_masks,
                                out_b);

    const int threads = 256;
    const int total   = (O_ / OB) * I4_;    // 524288 threads
    main_kernel<<<total / threads, threads>>>((const float4*)target_W,
                                              (const float4*)neighbor_W,
                                              (float4*)out);
}

// round 2
// speedup vs baseline: 1.1274x; 1.1274x over previous
#include <cuda_runtime.h>
#include <math.h>

#define N_ 32
#define O_ 2048
#define I_ 4096
#define I4_ (I_/4)          // 1024
#define E_ 3
#define D_ 8
#define H_ 16
#define SELF_W 0.7f
#define OB 4                // o-rows per thread

// Scratch (no allocs allowed)
__device__ float  g_w[N_];            // per-neighbor attention weight
__device__ float4 g_wnm4[N_ * I4_];   // w[n]*mask[n][i]/norm[i]
__device__ float4 g_a4[I4_];          // 0.7*tm[i]/norm[i]

// ---------------------------------------------------------------------------
// Kernel A: tiny MLPs + softmax -> g_w.  One warp.
// ---------------------------------------------------------------------------
__global__ void attn_kernel(const float* __restrict__ edge_feats,
                            const float* __restrict__ node_feats,
                            const float* __restrict__ W1e, const float* __restrict__ b1e,
                            const float* __restrict__ W2e, const float* __restrict__ b2e,
                            const float* __restrict__ W1n, const float* __restrict__ b1n,
                            const float* __restrict__ W2n, const float* __restrict__ b2n)
{
    const int n = threadIdx.x;
    if (n >= N_) return;

    float logit_e = b2e[0];
    #pragma unroll
    for (int h = 0; h < H_; h++) {
        float acc = b1e[h];
        #pragma unroll
        for (int e = 0; e < E_; e++)
            acc += edge_feats[n * E_ + e] * W1e[e * H_ + h];
        logit_e += tanhf(acc) * W2e[h];
    }
    const float score = 1.f / (1.f + expf(-logit_e));

    float logit_n = b2n[0];
    #pragma unroll
    for (int h = 0; h < H_; h++) {
        float acc = b1n[h];
        #pragma unroll
        for (int d = 0; d < D_; d++)
            acc += node_feats[n * D_ + d] * W1n[d * H_ + h];
        logit_n += tanhf(acc) * W2n[h];
    }
    const float cond = 1.f / (1.f + expf(-logit_n));

    const float s = score * cond;
    float m = s;
    #pragma unroll
    for (int off = 16; off; off >>= 1)
        m = fmaxf(m, __shfl_xor_sync(0xffffffffu, m, off));
    const float ex = expf(s - m);
    float sum = ex;
    #pragma unroll
    for (int off = 16; off; off >>= 1)
        sum += __shfl_xor_sync(0xffffffffu, sum, off);
    g_w[n] = (1.f - SELF_W) * ex / sum;
}

// ---------------------------------------------------------------------------
// Kernel B: per-column coefficients + bias output.  Fully parallel.
// grid.x covers I_ columns; extra blocks handle out_b.
// ---------------------------------------------------------------------------
__global__ void coeff_kernel(const int*   __restrict__ target_mask,
                             const int*   __restrict__ neighbor_masks,
                             const float* __restrict__ target_b,
                             const float* __restrict__ neighbor_b,
                             float* __restrict__ out_b)
{
    __shared__ float w_s[N_];
    if (threadIdx.x < N_) w_s[threadIdx.x] = g_w[threadIdx.x];
    __syncthreads();

    float* g_wnm = (float*)g_wnm4;
    float* g_a   = (float*)g_a4;

    const int i = blockIdx.x * blockDim.x + threadIdx.x;
    if (i < I_) {
        const float tm = (float)target_mask[i];
        float wn[N_];
        float norm = 1e-8f + SELF_W * tm;
        #pragma unroll
        for (int n = 0; n < N_; n++) {
            wn[n] = w_s[n] * (float)neighbor_masks[n * I_ + i];
            norm += wn[n];
        }
        const float inv = 1.f / norm;
        g_a[i] = SELF_W * tm * inv;
        #pragma unroll
        for (int n = 0; n < N_; n++)
            g_wnm[n * I_ + i] = wn[n] * inv;
    }

    // bias output: first 2048 "i" slots map 1:1 to o
    if (i < O_) {
        float acc = SELF_W * target_b[i];
        #pragma unroll
        for (int n = 0; n < N_; n++)
            acc += w_s[n] * neighbor_b[n * O_ + i];
        out_b[i] = acc;
    }
}

// ---------------------------------------------------------------------------
// Main: out_W[o,i] = target_W[o,i]*a[i] + sum_n wnm[n,i]*neighbor_W[n,o,i]
// Persistent grid-stride; OB o-rows per thread reuse the wnm tile.
// Streaming hints keep the 1 GB nW stream from thrashing L2.
// ---------------------------------------------------------------------------
#define MAIN_BLOCKS 592     // 148 SMs * 4 resident blocks
#define MAIN_THREADS 256

__global__ void __launch_bounds__(MAIN_THREADS)
main_kernel(const float4* __restrict__ tW,
            const float4* __restrict__ nW,
            float4* __restrict__ outW)
{
    const int total = (O_ / OB) * I4_;   // 524288 tiles
    for (int idx = blockIdx.x * MAIN_THREADS + threadIdx.x;
         idx < total;
         idx += MAIN_BLOCKS * MAIN_THREADS) {

        const int i4 = idx & (I4_ - 1);
        const int o0 = (idx >> 10) * OB;

        const float4 a = g_a4[i4];
        float4 acc[OB];
        #pragma unroll
        for (int oo = 0; oo < OB; oo++) {
            const float4 t = __ldcs(&tW[(size_t)(o0 + oo) * I4_ + i4]);
            acc[oo].x = t.x * a.x;
            acc[oo].y = t.y * a.y;
            acc[oo].z = t.z * a.z;
            acc[oo].w = t.w * a.w;
        }

        #pragma unroll 4
        for (int n = 0; n < N_; n++) {
            const float4 wv = g_wnm4[n * I4_ + i4];          // L2-resident (512 KB)
            const size_t base = (size_t)n * (O_ * I4_);
            #pragma unroll
            for (int oo = 0; oo < OB; oo++) {
                const float4 Wv = __ldcs(&nW[base + (size_t)(o0 + oo) * I4_ + i4]);
                acc[oo].x += wv.x * Wv.x;
                acc[oo].y += wv.y * Wv.y;
                acc[oo].z += wv.z * Wv.z;
                acc[oo].w += wv.w * Wv.w;
            }
        }

        #pragma unroll
        for (int oo = 0; oo < OB; oo++)
            __stcs(&outW[(size_t)(o0 + oo) * I4_ + i4], acc[oo]);
    }
}

// ---------------------------------------------------------------------------
extern "C" void kernel_launch(void* const* d_in, const int* in_sizes, int n_in,
                              void* d_out, int out_size)
{
    const float* edge_feats     = (const float*)d_in[0];
    const float* node_feats     = (const float*)d_in[1];
    const float* W1e            = (const float*)d_in[2];
    const float* b1e            = (const float*)d_in[3];
    const float* W2e            = (const float*)d_in[4];
    const float* b2e            = (const float*)d_in[5];
    const float* W1n            = (const float*)d_in[6];
    const float* b1n            = (const float*)d_in[7];
    const float* W2n            = (const float*)d_in[8];
    const float* b2n            = (const float*)d_in[9];
    const float* target_W       = (const float*)d_in[10];
    const float* neighbor_W     = (const float*)d_in[11];
    const float* target_b       = (const float*)d_in[12];
    const float* neighbor_b     = (const float*)d_in[13];
    const int*   target_mask    = (const int*)d_in[14];
    const int*   neighbor_masks = (const int*)d_in[15];

    float* out   = (float*)d_out;
    float* out_b = out + (size_t)O_ * I_;

    attn_kernel<<<1, 32>>>(edge_feats, node_feats,
                           W1e, b1e, W2e, b2e,
                           W1n, b1n, W2n, b2n);

    coeff_kernel<<<I_ / 256, 256>>>(target_mask, neighbor_masks,
                                    target_b, neighbor_b, out_b);

    main_kernel<<<MAIN_BLOCKS, MAIN_THREADS>>>((const float4*)target_W,
                                               (const float4*)neighbor_W,
                                               (float4*)out);
}